// round 15
// baseline (speedup 1.0000x reference)
#include <cuda_runtime.h>

// NeighborSample: x (8,64,64,192) f32 -> out (8*64*64, 5, 5, 192) f32
// out[pix][i][j][k] = x[b][y+i-2][x+j-2][k] (zero-padded)
//
// Flat coalesced mapping + ILP=8: each thread handles 8 float4 at stride
// blockDim (block covers 2048 consecutive float4 = 32KB contiguous output,
// 8 independent LDG->STG chains per thread). Every LDG/STG instruction is
// fully coalesced (512B/warp = 4 complete 128B lines).

#define C4    48u                      // 192 floats / 4
#define N4    39321600u                // 32768 * 25 * 48
#define ILP   8u
#define TPB   256u
#define GRID  (N4 / (ILP * TPB))       // 19200, exact

__global__ void __launch_bounds__(TPB) neighbor_sample_ilp8(
    const float4* __restrict__ in, float4* __restrict__ out)
{
    unsigned base = blockIdx.x * (ILP * TPB) + threadIdx.x;

    float4 v[ILP];

    // ---- gather: 8 independent decode+LDG chains, loads issue back-to-back ----
    #pragma unroll
    for (unsigned u = 0; u < ILP; u++) {
        unsigned idx = base + u * TPB;

        // decode: idx = (pix*25 + ij)*48 + k4
        unsigned k4  = idx % C4;
        unsigned r   = idx / C4;
        unsigned ij  = r % 25u;
        unsigned pix = r / 25u;
        unsigned j   = ij % 5u;
        unsigned i   = ij / 5u;

        unsigned xcol = pix & 63u;
        unsigned yrow = (pix >> 6) & 63u;
        unsigned b    = pix >> 12;

        int sy = (int)(yrow + i) - 2;
        int sx = (int)(xcol + j) - 2;

        v[u] = make_float4(0.f, 0.f, 0.f, 0.f);
        if ((unsigned)sy < 64u && (unsigned)sx < 64u) {
            unsigned src = ((((b << 6) + (unsigned)sy) << 6) | (unsigned)sx) * C4 + k4;
            v[u] = __ldg(&in[src]);
        }
    }

    // ---- store: 8 coalesced streaming stores, 32KB contiguous per block ----
    #pragma unroll
    for (unsigned u = 0; u < ILP; u++) {
        __stcs(&out[base + u * TPB], v[u]);
    }
}

extern "C" void kernel_launch(void* const* d_in, const int* in_sizes, int n_in,
                              void* d_out, int out_size)
{
    const float4* in  = (const float4*)d_in[0];
    float4*       out = (float4*)d_out;
    neighbor_sample_ilp8<<<GRID, TPB>>>(in, out);
}